// round 15
// baseline (speedup 1.0000x reference)
#include <cuda_runtime.h>
#include <cuda_fp16.h>
#include <cstdint>
#include <cstddef>

namespace {

constexpr int kB   = 4096;
constexpr int kN   = 64;
constexpr int kOBS = 192;
constexpr int kACT = 64;
constexpr int kIN  = 256;
constexpr int kD   = 128;
constexpr int kFO  = 64;

constexpr int kThreads = 1024;  // 32 warps: 2 groups x 16; group = one batch

// strides in __half units; word-step conflict-free (proven R13/R14)
constexpr int SA_LD = 264;
constexpr int E_LD  = 136;
constexpr int S_LD  = 72;
constexpr int WG_LD = 40;

// SMEM (halves): shared W0/W1 + two per-batch regions
constexpr int OFF_W0 = 0;
constexpr int OFF_W1 = 10240;
constexpr int OFF_B0 = 20480;
constexpr int BSTRIDE = 35328;  // per-batch region size
// within a batch region: SA @0 (16896) | T @0 (8704), VT @8704 (9216)
//                        SCH @0 (4608, after T dead) | H @0 (after SCH dead)
//                        E @17920 (8704) | EQ @26624 (8704)
constexpr int ROFF_SA = 0;
constexpr int ROFF_T  = 0;
constexpr int ROFF_VT = 8704;
constexpr int ROFF_SCH = 0;
constexpr int ROFF_H  = 0;
constexpr int ROFF_E  = 17920;
constexpr int ROFF_EQ = 26624;
constexpr int SMEM_HALVES = OFF_B0 + 2 * BSTRIDE;  // 91136
constexpr int SMEM_BYTES  = SMEM_HALVES * 2;       // 182272 (1 CTA/SM)

// Pre-packed fp16 weights (SMEM-image chunks of K=32) — unchanged from R14
constexpr int CHEE = 256 * WG_LD;
constexpr int CHS  = 64 * WG_LD;
constexpr int OPK_EE = 0;
constexpr int OPK_TV = 8 * CHEE;
constexpr int OPK_F1 = 12 * CHEE;
constexpr int OPK_F2 = OPK_F1 + 8 * CHS;
constexpr int PK_TOTAL = OPK_F2 + 2 * CHS;
__device__ __half gWP[PK_TOTAL];

__device__ __forceinline__ void mma16(float (&d)[4], const uint32_t (&a)[4],
                                      const uint32_t (&b)[2]) {
  asm volatile(
      "mma.sync.aligned.m16n8k16.row.col.f32.f16.f16.f32 "
      "{%0,%1,%2,%3}, {%4,%5,%6,%7}, {%8,%9}, {%0,%1,%2,%3};\n"
      : "+f"(d[0]), "+f"(d[1]), "+f"(d[2]), "+f"(d[3])
      : "r"(a[0]), "r"(a[1]), "r"(a[2]), "r"(a[3]), "r"(b[0]), "r"(b[1]));
}

__device__ __forceinline__ void ldsm_x4(uint32_t (&r)[4], uint32_t addr) {
  asm volatile(
      "ldmatrix.sync.aligned.m8n8.x4.shared.b16 {%0,%1,%2,%3}, [%4];"
      : "=r"(r[0]), "=r"(r[1]), "=r"(r[2]), "=r"(r[3]) : "r"(addr));
}
__device__ __forceinline__ void ldsm_x2(uint32_t (&r)[2], uint32_t addr) {
  asm volatile(
      "ldmatrix.sync.aligned.m8n8.x2.shared.b16 {%0,%1}, [%2];"
      : "=r"(r[0]), "=r"(r[1]) : "r"(addr));
}

// R14-proven ldmatrix fragment path (fp16 m16n8k16).
template <int NT, int KC>
__device__ __forceinline__ void mma_block(const __half* __restrict__ As, int lda,
                                          const __half* __restrict__ Bs, int ldb,
                                          float (&d)[2][NT][4],
                                          int lane, int wm, int wn) {
  const __half* Aw = As + (wm * 32) * lda;
  const __half* Bw = Bs + (wn * NT * 8) * ldb;
  const int l15 = lane & 15;
  const int ak = (lane >> 4) << 3;
  uint32_t a0ad = (uint32_t)__cvta_generic_to_shared(Aw + l15 * lda + ak);
  uint32_t a1ad = a0ad + (uint32_t)(16 * lda * sizeof(__half));
  const int bg = lane >> 3;
  const int brow = (lane & 7) + ((bg >> 1) << 3);
  const int bk = (bg & 1) << 3;
  uint32_t b0ad = (uint32_t)__cvta_generic_to_shared(Bw + brow * ldb + bk);
#pragma unroll
  for (int k0 = 0; k0 < KC; k0 += 16) {
    uint32_t a[2][4];
    ldsm_x4(a[0], a0ad + (uint32_t)(k0 * 2));
    ldsm_x4(a[1], a1ad + (uint32_t)(k0 * 2));
    if constexpr (NT == 1) {
      uint32_t bq[2];
      ldsm_x2(bq, b0ad + (uint32_t)(k0 * 2));
      mma16(d[0][0], a[0], bq);
      mma16(d[1][0], a[1], bq);
    } else {
#pragma unroll
      for (int np = 0; np < NT; np += 2) {
        uint32_t bq[4];
        ldsm_x4(bq, b0ad + (uint32_t)((np * 8 * ldb + k0) * 2));
        uint32_t blo[2] = {bq[0], bq[1]};
        uint32_t bhi[2] = {bq[2], bq[3]};
        mma16(d[0][np], a[0], blo);
        mma16(d[1][np], a[1], blo);
        mma16(d[0][np + 1], a[0], bhi);
        mma16(d[1][np + 1], a[1], bhi);
      }
    }
  }
}

template <int NT, class F>
__device__ __forceinline__ void for_each_pair(float (&d)[2][NT][4], int lane,
                                              int wm, int wn, F f) {
  const int gr = lane >> 2;
  const int gc2 = (lane & 3) * 2;
#pragma unroll
  for (int mt = 0; mt < 2; mt++)
#pragma unroll
    for (int nt = 0; nt < NT; nt++) {
      int col = wn * NT * 8 + nt * 8 + gc2;
      int row = wm * 32 + mt * 16 + gr;
      f(row, col, d[mt][nt][0], d[mt][nt][1]);
      f(row + 8, col, d[mt][nt][2], d[mt][nt][3]);
    }
}

template <int NT>
__device__ __forceinline__ void zero_acc(float (&d)[2][NT][4]) {
#pragma unroll
  for (int mt = 0; mt < 2; mt++)
#pragma unroll
    for (int nt = 0; nt < NT; nt++)
#pragma unroll
      for (int i = 0; i < 4; i++) d[mt][nt][i] = 0.f;
}

// ---- cp.async staging (all 1024 threads; ONE copy serves both batches)
__device__ __forceinline__ void cp16b(uint32_t saddr, const void* __restrict__ g) {
  asm volatile("cp.async.ca.shared.global [%0], [%1], 16;\n"
               :: "r"(saddr), "l"(g) : "memory");
}
template <int HCNT>
__device__ __forceinline__ void cpa_chunk(__half* dst, const __half* __restrict__ src,
                                          int tid) {
  uint32_t s0 = (uint32_t)__cvta_generic_to_shared(dst);
#pragma unroll
  for (int i = tid; i < HCNT / 8; i += kThreads)
    cp16b(s0 + (uint32_t)i * 16u, src + i * 8);
  asm volatile("cp.async.commit_group;\n" ::: "memory");
}
__device__ __forceinline__ void cpa_wait() {
  asm volatile("cp.async.wait_group 0;\n" ::: "memory");
}

// Double-buffered staged matmul; A is the calling group's batch region.
template <int NT, int NCH, int HCNT>
__device__ __forceinline__ void staged_mm(const __half* __restrict__ A, int lda,
                                          const __half* __restrict__ wsrc,
                                          float (&d)[2][NT][4],
                                          __half* w0, __half* w1, int tid,
                                          int lane, int wm, int wn) {
  cpa_chunk<HCNT>(w0, wsrc, tid);
  cpa_wait();
  __syncthreads();
#pragma unroll
  for (int c = 0; c < NCH; c++) {
    __half* cur = (c & 1) ? w1 : w0;
    __half* nxt = (c & 1) ? w0 : w1;
    const bool more = (c + 1 < NCH);
    if (more) cpa_chunk<HCNT>(nxt, wsrc + (c + 1) * HCNT, tid);
    mma_block<NT, 32>(A + c * 32, lda, cur, WG_LD, d, lane, wm, wn);
    if (more) cpa_wait();
    __syncthreads();
  }
}

// ---- prologue kernels (unchanged from R14)
__global__ void pack_w(const float* __restrict__ W, int On, int Kfull,
                       int nch, int dst_off, int chunk_rows, int row_base) {
  int idx = blockIdx.x * 256 + threadIdx.x;
  int total = nch * On * 32;
  if (idx >= total) return;
  int c = idx / (On * 32);
  int rem = idx - c * (On * 32);
  int o = rem >> 5, k = rem & 31;
  gWP[dst_off + c * chunk_rows * WG_LD + (row_base + o) * WG_LD + k] =
      __float2half_rn(W[o * Kfull + c * 32 + k]);
}

__global__ void precompute_mt(const float* __restrict__ Wq,
                              const float* __restrict__ Wk) {
  __shared__ float wkj[kD];
  const int j = blockIdx.x;
  const int i = threadIdx.x;
  wkj[i] = Wk[i * kD + j];
  __syncthreads();
  float s = 0.f;
#pragma unroll 8
  for (int dd = 0; dd < kD; dd++) s += Wq[dd * kD + i] * wkj[dd];
  int c = i >> 5, k = i & 31;
  gWP[OPK_TV + c * CHEE + j * WG_LD + k] = __float2half_rn(s);
}

__global__ __launch_bounds__(kThreads, 1)
void critic_kernel(const float* __restrict__ states,
                   const float* __restrict__ actions,
                   const float* __restrict__ b_embed,
                   const float* __restrict__ b_embed_q,
                   float* __restrict__ outV,
                   float* __restrict__ outW) {
  extern __shared__ __half smem[];
  const int tid = threadIdx.x;
  const int lane = tid & 31;
  const int warp = tid >> 5;
  const int grp = warp >> 4;               // batch group 0/1
  const int wg = warp & 15;                // warp within group
  const int wm = wg >> 3, wn = wg & 7;     // 16-warp grid per batch
  const size_t b = (size_t)blockIdx.x * 2 + grp;  // this group's batch

  __half* W0 = smem + OFF_W0;
  __half* W1 = smem + OFF_W1;
  __half* BR = smem + OFF_B0 + grp * BSTRIDE;  // this group's batch region
  __half* SA = BR + ROFF_SA;
  __half* T  = BR + ROFF_T;
  __half* VT = BR + ROFF_VT;
  __half* SCH = BR + ROFF_SCH;
  __half* H  = BR + ROFF_H;
  __half* E  = BR + ROFF_E;
  __half* EQ = BR + ROFF_EQ;
  // fp32 scores: batch0 in W0, batch1 in W1 (W idle during scores/softmax/x)
  float* SCf = reinterpret_cast<float*>(grp ? W1 : W0);

  // ---- load sa for BOTH batches (all 1024 threads)
  {
#pragma unroll 4
    for (int j = 0; j < 32; j++) {
      int i = tid + j * kThreads;
      int g = i >> 14;               // 2 x 64 x 256 items
      int t = (i >> 8) & 63;
      int c = i & 255;
      size_t bb = (size_t)blockIdx.x * 2 + g;
      float v = (c < kOBS) ? states[(bb * kN + t) * kOBS + c]
                           : actions[(bb * kN + t) * kACT + (c - kOBS)];
      smem[OFF_B0 + g * BSTRIDE + ROFF_SA + t * SA_LD + c] = __float2half_rn(v);
    }
  }

  float d4[2][4][4];
  float d2[2][2][4];
  float d1[2][1][4];

  // ======== merged e|eq: [64,256] = sa @ [We;Weq]^T ======================
  zero_acc(d4);
  staged_mm<4, 8, CHEE>(SA, SA_LD, gWP + OPK_EE, d4, W0, W1, tid, lane, wm, wn);
  if (wn < 4) {
    for_each_pair<4>(d4, lane, wm, wn, [&](int r, int c, float lo, float hi) {
      lo += __ldg(b_embed + c);
      hi += __ldg(b_embed + c + 1);
      lo = lo > 0.f ? lo : 0.01f * lo;
      hi = hi > 0.f ? hi : 0.01f * hi;
      *(__half2*)(E + r * E_LD + c) = __floats2half2_rn(lo, hi);
    });
  } else {
    for_each_pair<4>(d4, lane, wm, wn, [&](int r, int c, float lo, float hi) {
      int cl = c - 128;
      lo += __ldg(b_embed_q + cl);
      hi += __ldg(b_embed_q + cl + 1);
      lo = lo > 0.f ? lo : 0.01f * lo;
      hi = hi > 0.f ? hi : 0.01f * hi;
      *(__half2*)(EQ + r * E_LD + cl) = __floats2half2_rn(lo, hi);
    });
  }
  __syncthreads();  // E/EQ complete; SA dead

  // ======== merged t|v: [64,256] = e @ [Mt;Wv]^T =========================
  zero_acc(d4);
  staged_mm<4, 4, CHEE>(E, E_LD, gWP + OPK_TV, d4, W0, W1, tid, lane, wm, wn);
  if (wn < 4) {
    for_each_pair<4>(d4, lane, wm, wn, [&](int r, int c, float lo, float hi) {
      *(__half2*)(T + r * E_LD + c) = __floats2half2_rn(lo, hi);
    });
  } else {
    for_each_pair<4>(d4, lane, wm, wn, [&](int r, int c, float lo, float hi) {
      int cl = c - 128;
      VT[cl * S_LD + r] = __float2half_rn(lo);
      VT[(cl + 1) * S_LD + r] = __float2half_rn(hi);
    });
  }
  __syncthreads();  // T, VT visible; W buffers idle -> SCf may alias

  // ======== scores = t @ e^T / sqrt(D) -> SCf fp32 =======================
  zero_acc(d1);
  mma_block<1, 128>(T, E_LD, E, E_LD, d1, lane, wm, wn);
  for_each_pair<1>(d1, lane, wm, wn, [&](int r, int c, float lo, float hi) {
    *(float2*)(SCf + r * S_LD + c) =
        make_float2(lo * 0.08838834764831845f, hi * 0.08838834764831845f);
  });
  __syncthreads();

  // ======== row softmax: 1024 threads = 2 batches x 64 rows x 8 lanes ====
  {
    const int g = tid >> 9;
    const int r = (tid >> 3) & 63;
    const int c0 = (tid & 7) * 8;
    float* scf_g = reinterpret_cast<float*>(g ? W1 : W0);
    __half* sch_g = smem + OFF_B0 + g * BSTRIDE + ROFF_SCH;
    const float* wrow = scf_g + r * S_LD + c0;
    float s[8];
#pragma unroll
    for (int j = 0; j < 8; j++) s[j] = wrow[j];
    float mx = -3.0e38f;
#pragma unroll
    for (int j = 0; j < 8; j++) mx = fmaxf(mx, s[j]);
    mx = fmaxf(mx, __shfl_xor_sync(0xffffffffu, mx, 1));
    mx = fmaxf(mx, __shfl_xor_sync(0xffffffffu, mx, 2));
    mx = fmaxf(mx, __shfl_xor_sync(0xffffffffu, mx, 4));
    float sum = 0.f;
#pragma unroll
    for (int j = 0; j < 8; j++) {
      s[j] = __expf(s[j] - mx);
      sum += s[j];
    }
    sum += __shfl_xor_sync(0xffffffffu, sum, 1);
    sum += __shfl_xor_sync(0xffffffffu, sum, 2);
    sum += __shfl_xor_sync(0xffffffffu, sum, 4);
    float inv = 1.f / sum;
    size_t bb = (size_t)blockIdx.x * 2 + g;
    float* og = outW + (bb * kN + r) * kN + c0;
#pragma unroll
    for (int j = 0; j < 8; j++) {
      float wv = s[j] * inv;
      og[j] = wv;
      sch_g[r * S_LD + c0 + j] = __float2half_rn(wv);
    }
  }
  __syncthreads();

  // ======== x = weight @ v -> E ==========================================
  zero_acc(d2);
  mma_block<2, 64>(SCH, S_LD, VT, S_LD, d2, lane, wm, wn);
  for_each_pair<2>(d2, lane, wm, wn, [&](int r, int c, float lo, float hi) {
    *(__half2*)(E + r * E_LD + c) = __floats2half2_rn(lo, hi);
  });
  __syncthreads();  // x done; SCf/SCH dead -> staging resumes

  // ======== h = lrelu([eq, x] @ W_f1^T) ==================================
  zero_acc(d1);
  staged_mm<1, 4, CHS>(EQ, E_LD, gWP + OPK_F1, d1, W0, W0 + 5120, tid, lane,
                       wm, wn);
  staged_mm<1, 4, CHS>(E, E_LD, gWP + OPK_F1 + 4 * CHS, d1, W0, W0 + 5120,
                       tid, lane, wm, wn);
  for_each_pair<1>(d1, lane, wm, wn, [&](int r, int c, float lo, float hi) {
    lo = lo > 0.f ? lo : 0.01f * lo;
    hi = hi > 0.f ? hi : 0.01f * hi;
    *(__half2*)(H + r * S_LD + c) = __floats2half2_rn(lo, hi);  // SCH dead
  });

  // ======== Value = h @ W_f2^T -> gmem ===================================
  zero_acc(d1);
  staged_mm<1, 2, CHS>(H, S_LD, gWP + OPK_F2, d1, W0, W0 + 5120, tid, lane,
                       wm, wn);
  for_each_pair<1>(d1, lane, wm, wn, [&](int r, int c, float lo, float hi) {
    *(float2*)(outV + (b * kN + r) * kFO + c) = make_float2(lo, hi);
  });
}

}  // namespace

extern "C" void kernel_launch(void* const* d_in, const int* in_sizes, int n_in,
                              void* d_out, int out_size) {
  (void)in_sizes; (void)n_in; (void)out_size;
  const float* states    = (const float*)d_in[0];
  const float* actions   = (const float*)d_in[1];
  const float* W_embed   = (const float*)d_in[2];
  const float* b_embed   = (const float*)d_in[3];
  const float* W_k       = (const float*)d_in[4];
  const float* W_q       = (const float*)d_in[5];
  const float* W_v       = (const float*)d_in[6];
  const float* W_embed_q = (const float*)d_in[7];
  const float* b_embed_q = (const float*)d_in[8];
  const float* W_f1      = (const float*)d_in[9];
  const float* W_f2      = (const float*)d_in[10];

  float* outV = (float*)d_out;                 // Value [B,N,64]
  float* outW = outV + (size_t)kB * kN * kFO;  // weight [B,N,N]

  precompute_mt<<<kD, kD>>>(W_q, W_k);
  pack_w<<<(8 * 128 * 32 + 255) / 256, 256>>>(W_embed, 128, kIN, 8, OPK_EE,
                                              256, 0);
  pack_w<<<(8 * 128 * 32 + 255) / 256, 256>>>(W_embed_q, 128, kIN, 8, OPK_EE,
                                              256, 128);
  pack_w<<<(4 * 128 * 32 + 255) / 256, 256>>>(W_v, 128, kD, 4, OPK_TV,
                                              256, 128);
  pack_w<<<(8 * 64 * 32 + 255) / 256, 256>>>(W_f1, 64, 2 * kD, 8, OPK_F1,
                                             64, 0);
  pack_w<<<(2 * 64 * 32 + 255) / 256, 256>>>(W_f2, 64, kN, 2, OPK_F2,
                                             64, 0);

  cudaFuncSetAttribute(critic_kernel,
                       cudaFuncAttributeMaxDynamicSharedMemorySize, SMEM_BYTES);
  critic_kernel<<<kB / 2, kThreads, SMEM_BYTES>>>(states, actions, b_embed,
                                                  b_embed_q, outV, outW);
}

// round 17
// speedup vs baseline: 1.4325x; 1.4325x over previous
#include <cuda_runtime.h>
#include <cuda_fp16.h>
#include <cstdint>
#include <cstddef>

namespace {

constexpr int kB   = 4096;
constexpr int kN   = 64;
constexpr int kOBS = 192;
constexpr int kACT = 64;
constexpr int kIN  = 256;
constexpr int kD   = 128;
constexpr int kFO  = 64;

constexpr int kThreads = 512;  // 16 warps; 2 CTAs per SM

// strides in __half units (proven R13/R14)
constexpr int SA_LD = 264;
constexpr int E_LD  = 136;
constexpr int S_LD  = 72;
constexpr int WG_LD = 40;  // pack-kernel SMEM image stride (R14-proven)

// SMEM (halves), 44544 h = 89088 B -> 2 CTAs/SM
constexpr int OFF_SA  = 0;      // sa (dead after e|eq)
constexpr int OFF_T   = 0;      // t (dead after scores)
constexpr int OFF_VT  = 8704;   // v^T [128x72]
constexpr int OFF_SCH = 0;      // fp16 softmax weights (over dead T)
constexpr int OFF_H   = 0;      // h (over dead SCH)
constexpr int OFF_E   = 17920;  // e; later x
constexpr int OFF_EQ  = 26624;  // eq
constexpr int OFF_SCF = 35328;  // fp32 scores (9216 halves)
constexpr int SMEM_HALVES = 44544;
constexpr int SMEM_BYTES  = SMEM_HALVES * 2;  // 89088

// Fragment-ordered weights in GMEM.
constexpr int CH4 = 8192;   // halves per 256-col NT4 chunk
constexpr int CH1 = 2048;   // halves per 64-col NT1 chunk
constexpr int OPK_EE = 0;                   // 8 chunks
constexpr int OPK_TV = 8 * CH4;             // 4 chunks
constexpr int OPK_F1 = 12 * CH4;            // 8 chunks
constexpr int OPK_F2 = OPK_F1 + 8 * CH1;    // 2 chunks
constexpr int PK_TOTAL = OPK_F2 + 2 * CH1;
__device__ __half gWB[PK_TOTAL];
__device__ float gMtF[kD * kD];

__device__ __forceinline__ void mma16(float (&d)[4], const uint32_t (&a)[4],
                                      const uint32_t (&b)[2]) {
  asm volatile(
      "mma.sync.aligned.m16n8k16.row.col.f32.f16.f16.f32 "
      "{%0,%1,%2,%3}, {%4,%5,%6,%7}, {%8,%9}, {%0,%1,%2,%3};\n"
      : "+f"(d[0]), "+f"(d[1]), "+f"(d[2]), "+f"(d[3])
      : "r"(a[0]), "r"(a[1]), "r"(a[2]), "r"(a[3]), "r"(b[0]), "r"(b[1]));
}

__device__ __forceinline__ void ldsm_x4(uint32_t (&r)[4], uint32_t addr) {
  asm volatile(
      "ldmatrix.sync.aligned.m8n8.x4.shared.b16 {%0,%1,%2,%3}, [%4];"
      : "=r"(r[0]), "=r"(r[1]), "=r"(r[2]), "=r"(r[3]) : "r"(addr));
}
__device__ __forceinline__ void ldsm_x2(uint32_t (&r)[2], uint32_t addr) {
  asm volatile(
      "ldmatrix.sync.aligned.m8n8.x2.shared.b16 {%0,%1}, [%2];"
      : "=r"(r[0]), "=r"(r[1]) : "r"(addr));
}

// ---- A-fragment loader (R14-proven), one K=32 chunk, sub-step s in {0,1}
__device__ __forceinline__ void load_a(uint32_t (&a)[2][4],
                                       const __half* __restrict__ Aw, int lda,
                                       int lane, int s) {
  const int l15 = lane & 15;
  const int ak = (lane >> 4) << 3;
  uint32_t a0 = (uint32_t)__cvta_generic_to_shared(Aw + l15 * lda + ak + s * 16);
  ldsm_x4(a[0], a0);
  ldsm_x4(a[1], a0 + (uint32_t)(16 * lda * sizeof(__half)));
}

// ---- NT4 chunk with B fragments from gmem (fragment order, by construction)
__device__ __forceinline__ void mma_g4(const __half* __restrict__ Aw, int lda,
                                       const uint4* __restrict__ B4c,
                                       float (&d)[2][4][4], int lane, int wn) {
#pragma unroll
  for (int s = 0; s < 2; s++) {
    uint32_t a[2][4];
    load_a(a, Aw, lda, lane, s);
    uint4 p0 = __ldg(&B4c[(((s * 8 + wn) * 2 + 0) * 32) + lane]);
    uint4 p1 = __ldg(&B4c[(((s * 8 + wn) * 2 + 1) * 32) + lane]);
    {
      uint32_t blo[2] = {p0.x, p0.y};
      uint32_t bhi[2] = {p0.z, p0.w};
      mma16(d[0][0], a[0], blo);
      mma16(d[1][0], a[1], blo);
      mma16(d[0][1], a[0], bhi);
      mma16(d[1][1], a[1], bhi);
    }
    {
      uint32_t blo[2] = {p1.x, p1.y};
      uint32_t bhi[2] = {p1.z, p1.w};
      mma16(d[0][2], a[0], blo);
      mma16(d[1][2], a[1], blo);
      mma16(d[0][3], a[0], bhi);
      mma16(d[1][3], a[1], bhi);
    }
  }
}

// ---- NT1 chunk: uint2 per lane per s
__device__ __forceinline__ void mma_g1(const __half* __restrict__ Aw, int lda,
                                       const uint2* __restrict__ B2c,
                                       float (&d)[2][1][4], int lane, int wn) {
#pragma unroll
  for (int s = 0; s < 2; s++) {
    uint32_t a[2][4];
    load_a(a, Aw, lda, lane, s);
    uint2 p = __ldg(&B2c[((s * 8 + wn) * 32) + lane]);
    uint32_t b[2] = {p.x, p.y};
    mma16(d[0][0], a[0], b);
    mma16(d[1][0], a[1], b);
  }
}

// ---- SMEM-B mma (scores, x): R14-proven ldmatrix path.
template <int NT, int KC>
__device__ __forceinline__ void mma_block(const __half* __restrict__ As, int lda,
                                          const __half* __restrict__ Bs, int ldb,
                                          float (&d)[2][NT][4],
                                          int lane, int wm, int wn) {
  const __half* Aw = As + (wm * 32) * lda;
  const __half* Bw = Bs + (wn * NT * 8) * ldb;
  const int l15 = lane & 15;
  const int ak = (lane >> 4) << 3;
  uint32_t a0ad = (uint32_t)__cvta_generic_to_shared(Aw + l15 * lda + ak);
  uint32_t a1ad = a0ad + (uint32_t)(16 * lda * sizeof(__half));
  const int bg = lane >> 3;
  const int brow = (lane & 7) + ((bg >> 1) << 3);
  const int bk = (bg & 1) << 3;
  uint32_t b0ad = (uint32_t)__cvta_generic_to_shared(Bw + brow * ldb + bk);
#pragma unroll
  for (int k0 = 0; k0 < KC; k0 += 16) {
    uint32_t a[2][4];
    ldsm_x4(a[0], a0ad + (uint32_t)(k0 * 2));
    ldsm_x4(a[1], a1ad + (uint32_t)(k0 * 2));
    if constexpr (NT == 1) {
      uint32_t bq[2];
      ldsm_x2(bq, b0ad + (uint32_t)(k0 * 2));
      mma16(d[0][0], a[0], bq);
      mma16(d[1][0], a[1], bq);
    } else {
#pragma unroll
      for (int np = 0; np < NT; np += 2) {
        uint32_t bq[4];
        ldsm_x4(bq, b0ad + (uint32_t)((np * 8 * ldb + k0) * 2));
        uint32_t blo[2] = {bq[0], bq[1]};
        uint32_t bhi[2] = {bq[2], bq[3]};
        mma16(d[0][np], a[0], blo);
        mma16(d[1][np], a[1], blo);
        mma16(d[0][np + 1], a[0], bhi);
        mma16(d[1][np + 1], a[1], bhi);
      }
    }
  }
}

template <int NT, class F>
__device__ __forceinline__ void for_each_pair(float (&d)[2][NT][4], int lane,
                                              int wm, int wn, F f) {
  const int gr = lane >> 2;
  const int gc2 = (lane & 3) * 2;
#pragma unroll
  for (int mt = 0; mt < 2; mt++)
#pragma unroll
    for (int nt = 0; nt < NT; nt++) {
      int col = wn * NT * 8 + nt * 8 + gc2;
      int row = wm * 32 + mt * 16 + gr;
      f(row, col, d[mt][nt][0], d[mt][nt][1]);
      f(row + 8, col, d[mt][nt][2], d[mt][nt][3]);
    }
}

template <int NT>
__device__ __forceinline__ void zero_acc(float (&d)[2][NT][4]) {
#pragma unroll
  for (int mt = 0; mt < 2; mt++)
#pragma unroll
    for (int nt = 0; nt < NT; nt++)
#pragma unroll
      for (int i = 0; i < 4; i++) d[mt][nt][i] = 0.f;
}

// ============ pack kernels: BY CONSTRUCTION (run the proven loader) ========
// One block per K=32 chunk. Stage the chunk into the R14 SMEM image, then
// each warp (wn) executes the EXACT R14 B-fragment loads and stores the
// registers at the consumer's indices.
__global__ void pack4(const float* __restrict__ Wlo,
                      const float* __restrict__ Whi, int Klo, int Khi,
                      int dst_off) {
  __shared__ __half sw[256 * WG_LD];
  const int c = blockIdx.x;
  const int tid = threadIdx.x;  // 256 threads
#pragma unroll
  for (int j = 0; j < 32; j++) {
    int i = tid + j * 256;
    int o = i >> 5, k = i & 31;
    float v = (o < 128) ? Wlo[o * Klo + c * 32 + k]
                        : Whi[(o - 128) * Khi + c * 32 + k];
    sw[o * WG_LD + k] = __float2half_rn(v);
  }
  __syncthreads();
  const int lane = tid & 31;
  const int wn = tid >> 5;  // 8 warps
  const __half* Bw = sw + (wn * 32) * WG_LD;  // NT=4: wn*NT*8
  const int bg = lane >> 3;
  const int brow = (lane & 7) + ((bg >> 1) << 3);
  const int bk = (bg & 1) << 3;
  uint32_t b0ad = (uint32_t)__cvta_generic_to_shared(Bw + brow * WG_LD + bk);
  uint4* dst = reinterpret_cast<uint4*>(gWB + dst_off) + c * (CH4 / 8);
#pragma unroll
  for (int s = 0; s < 2; s++) {
#pragma unroll
    for (int pp = 0; pp < 2; pp++) {
      uint32_t bq[4];
      // identical to R14: offset (np*8*ldb + k0)*2 bytes, np=2*pp, k0=16*s
      ldsm_x4(bq, b0ad + (uint32_t)(((pp * 2) * 8 * WG_LD + s * 16) * 2));
      dst[(((s * 8 + wn) * 2 + pp) * 32) + lane] =
          make_uint4(bq[0], bq[1], bq[2], bq[3]);
    }
  }
}

__global__ void pack1(const float* __restrict__ W, int Kfull, int dst_off) {
  __shared__ __half sw[64 * WG_LD];
  const int c = blockIdx.x;
  const int tid = threadIdx.x;  // 256 threads
#pragma unroll
  for (int j = 0; j < 8; j++) {
    int i = tid + j * 256;
    int o = i >> 5, k = i & 31;
    sw[o * WG_LD + k] = __float2half_rn(W[o * Kfull + c * 32 + k]);
  }
  __syncthreads();
  const int lane = tid & 31;
  const int wn = tid >> 5;
  const __half* Bw = sw + (wn * 8) * WG_LD;  // NT=1: wn*NT*8
  const int bg = lane >> 3;
  const int brow = (lane & 7) + ((bg >> 1) << 3);
  const int bk = (bg & 1) << 3;
  uint32_t b0ad = (uint32_t)__cvta_generic_to_shared(Bw + brow * WG_LD + bk);
  uint2* dst = reinterpret_cast<uint2*>(gWB + dst_off) + c * (CH1 / 4);
#pragma unroll
  for (int s = 0; s < 2; s++) {
    uint32_t bq[2];
    ldsm_x2(bq, b0ad + (uint32_t)((s * 16) * 2));
    dst[((s * 8 + wn) * 32) + lane] = make_uint2(bq[0], bq[1]);
  }
}

__global__ void precompute_mt(const float* __restrict__ Wq,
                              const float* __restrict__ Wk) {
  __shared__ float wkj[kD];
  const int j = blockIdx.x;
  const int i = threadIdx.x;
  wkj[i] = Wk[i * kD + j];
  __syncthreads();
  float s = 0.f;
#pragma unroll 8
  for (int dd = 0; dd < kD; dd++) s += Wq[dd * kD + i] * wkj[dd];
  gMtF[j * kD + i] = s;
}

__global__ __launch_bounds__(kThreads, 2)
void critic_kernel(const float* __restrict__ states,
                   const float* __restrict__ actions,
                   const float* __restrict__ b_embed,
                   const float* __restrict__ b_embed_q,
                   float* __restrict__ outV,
                   float* __restrict__ outW) {
  extern __shared__ __half smem[];
  const int b = blockIdx.x;
  const int tid = threadIdx.x;
  const int lane = tid & 31;
  const int warp = tid >> 5;
  const int wm = warp >> 3, wn = warp & 7;

  __half* SA  = smem + OFF_SA;
  __half* T   = smem + OFF_T;
  __half* VT  = smem + OFF_VT;
  __half* SCH = smem + OFF_SCH;
  __half* H   = smem + OFF_H;
  __half* E   = smem + OFF_E;
  __half* EQ  = smem + OFF_EQ;
  float*  SCF = reinterpret_cast<float*>(smem + OFF_SCF);

  // ---- load sa as fp16
  {
    const float* st = states + (size_t)b * kN * kOBS;
    const float* ac = actions + (size_t)b * kN * kACT;
#pragma unroll 4
    for (int j = 0; j < 32; j++) {
      int i = tid + j * kThreads;
      int t = i >> 8, c = i & 255;
      float v = (c < kOBS) ? st[t * kOBS + c] : ac[t * kACT + (c - kOBS)];
      SA[t * SA_LD + c] = __float2half_rn(v);
    }
  }
  __syncthreads();

  float d4[2][4][4];
  float d2[2][2][4];
  float d1[2][1][4];

  const __half* Awm;

  // ======== merged e|eq: [64,256] = sa @ [We;Weq]^T — no internal syncs ==
  zero_acc(d4);
  Awm = SA + (wm * 32) * SA_LD;
  {
    const uint4* B4 = reinterpret_cast<const uint4*>(gWB + OPK_EE);
#pragma unroll
    for (int c = 0; c < 8; c++)
      mma_g4(Awm + c * 32, SA_LD, B4 + c * (CH4 / 8), d4, lane, wn);
  }
  if (wn < 4) {
    for_each_pair<4>(d4, lane, wm, wn, [&](int r, int c, float lo, float hi) {
      lo += __ldg(b_embed + c);
      hi += __ldg(b_embed + c + 1);
      lo = lo > 0.f ? lo : 0.01f * lo;
      hi = hi > 0.f ? hi : 0.01f * hi;
      *(__half2*)(E + r * E_LD + c) = __floats2half2_rn(lo, hi);
    });
  } else {
    for_each_pair<4>(d4, lane, wm, wn, [&](int r, int c, float lo, float hi) {
      int cl = c - 128;
      lo += __ldg(b_embed_q + cl);
      hi += __ldg(b_embed_q + cl + 1);
      lo = lo > 0.f ? lo : 0.01f * lo;
      hi = hi > 0.f ? hi : 0.01f * hi;
      *(__half2*)(EQ + r * E_LD + cl) = __floats2half2_rn(lo, hi);
    });
  }
  __syncthreads();

  // ======== merged t|v: [64,256] = e @ [Mt;Wv]^T =========================
  zero_acc(d4);
  Awm = E + (wm * 32) * E_LD;
  {
    const uint4* B4 = reinterpret_cast<const uint4*>(gWB + OPK_TV);
#pragma unroll
    for (int c = 0; c < 4; c++)
      mma_g4(Awm + c * 32, E_LD, B4 + c * (CH4 / 8), d4, lane, wn);
  }
  if (wn < 4) {
    for_each_pair<4>(d4, lane, wm, wn, [&](int r, int c, float lo, float hi) {
      *(__half2*)(T + r * E_LD + c) = __floats2half2_rn(lo, hi);
    });
  } else {
    for_each_pair<4>(d4, lane, wm, wn, [&](int r, int c, float lo, float hi) {
      int cl = c - 128;
      VT[cl * S_LD + r] = __float2half_rn(lo);
      VT[(cl + 1) * S_LD + r] = __float2half_rn(hi);
    });
  }
  __syncthreads();

  // ======== scores = t @ e^T / sqrt(D) -> SCF fp32 =======================
  zero_acc(d1);
  mma_block<1, 128>(T, E_LD, E, E_LD, d1, lane, wm, wn);
  for_each_pair<1>(d1, lane, wm, wn, [&](int r, int c, float lo, float hi) {
    *(float2*)(SCF + r * S_LD + c) =
        make_float2(lo * 0.08838834764831845f, hi * 0.08838834764831845f);
  });
  __syncthreads();

  // ======== row softmax: gmem fp32 + fp16 copy into SCH ==================
  {
    const int r = tid >> 3;
    const int c0 = (tid & 7) * 8;
    const float* wrow = SCF + r * S_LD + c0;
    float s[8];
#pragma unroll
    for (int j = 0; j < 8; j++) s[j] = wrow[j];
    float mx = -3.0e38f;
#pragma unroll
    for (int j = 0; j < 8; j++) mx = fmaxf(mx, s[j]);
    mx = fmaxf(mx, __shfl_xor_sync(0xffffffffu, mx, 1));
    mx = fmaxf(mx, __shfl_xor_sync(0xffffffffu, mx, 2));
    mx = fmaxf(mx, __shfl_xor_sync(0xffffffffu, mx, 4));
    float sum = 0.f;
#pragma unroll
    for (int j = 0; j < 8; j++) {
      s[j] = __expf(s[j] - mx);
      sum += s[j];
    }
    sum += __shfl_xor_sync(0xffffffffu, sum, 1);
    sum += __shfl_xor_sync(0xffffffffu, sum, 2);
    sum += __shfl_xor_sync(0xffffffffu, sum, 4);
    float inv = 1.f / sum;
    float* og = outW + ((size_t)b * kN + r) * kN + c0;
#pragma unroll
    for (int j = 0; j < 8; j++) {
      float wv = s[j] * inv;
      og[j] = wv;
      SCH[r * S_LD + c0 + j] = __float2half_rn(wv);
    }
  }
  __syncthreads();

  // ======== x = weight @ v -> E ==========================================
  zero_acc(d2);
  mma_block<2, 64>(SCH, S_LD, VT, S_LD, d2, lane, wm, wn);
  for_each_pair<2>(d2, lane, wm, wn, [&](int r, int c, float lo, float hi) {
    *(__half2*)(E + r * E_LD + c) = __floats2half2_rn(lo, hi);
  });
  __syncthreads();

  // ======== h = lrelu([eq, x] @ W_f1^T) — no internal syncs ==============
  zero_acc(d1);
  {
    const uint2* B2 = reinterpret_cast<const uint2*>(gWB + OPK_F1);
    const __half* A0 = EQ + (wm * 32) * E_LD;
    const __half* A1 = E + (wm * 32) * E_LD;
#pragma unroll
    for (int c = 0; c < 4; c++)
      mma_g1(A0 + c * 32, E_LD, B2 + c * (CH1 / 4), d1, lane, wn);
#pragma unroll
    for (int c = 0; c < 4; c++)
      mma_g1(A1 + c * 32, E_LD, B2 + (4 + c) * (CH1 / 4), d1, lane, wn);
  }
  for_each_pair<1>(d1, lane, wm, wn, [&](int r, int c, float lo, float hi) {
    lo = lo > 0.f ? lo : 0.01f * lo;
    hi = hi > 0.f ? hi : 0.01f * hi;
    *(__half2*)(H + r * S_LD + c) = __floats2half2_rn(lo, hi);
  });
  __syncthreads();

  // ======== Value = h @ W_f2^T -> gmem ===================================
  zero_acc(d1);
  {
    const uint2* B2 = reinterpret_cast<const uint2*>(gWB + OPK_F2);
    const __half* A0 = H + (wm * 32) * S_LD;
#pragma unroll
    for (int c = 0; c < 2; c++)
      mma_g1(A0 + c * 32, S_LD, B2 + c * (CH1 / 4), d1, lane, wn);
  }
  for_each_pair<1>(d1, lane, wm, wn, [&](int r, int c, float lo, float hi) {
    *(float2*)(outV + ((size_t)b * kN + r) * kFO + c) = make_float2(lo, hi);
  });
}

}  // namespace

extern "C" void kernel_launch(void* const* d_in, const int* in_sizes, int n_in,
                              void* d_out, int out_size) {
  (void)in_sizes; (void)n_in; (void)out_size;
  const float* states    = (const float*)d_in[0];
  const float* actions   = (const float*)d_in[1];
  const float* W_embed   = (const float*)d_in[2];
  const float* b_embed   = (const float*)d_in[3];
  const float* W_k       = (const float*)d_in[4];
  const float* W_q       = (const float*)d_in[5];
  const float* W_v       = (const float*)d_in[6];
  const float* W_embed_q = (const float*)d_in[7];
  const float* b_embed_q = (const float*)d_in[8];
  const float* W_f1      = (const float*)d_in[9];
  const float* W_f2      = (const float*)d_in[10];

  float* outV = (float*)d_out;                 // Value [B,N,64]
  float* outW = outV + (size_t)kB * kN * kFO;  // weight [B,N,N]

  float* mtf = nullptr;
  cudaGetSymbolAddress((void**)&mtf, gMtF);

  precompute_mt<<<kD, kD>>>(W_q, W_k);
  pack4<<<8, 256>>>(W_embed, W_embed_q, kIN, kIN, OPK_EE);
  pack4<<<4, 256>>>(mtf, W_v, kD, kD, OPK_TV);
  pack1<<<8, 256>>>(W_f1, 2 * kD, OPK_F1);
  pack1<<<2, 256>>>(W_f2, kN, OPK_F2);

  cudaFuncSetAttribute(critic_kernel,
                       cudaFuncAttributeMaxDynamicSharedMemorySize, SMEM_BYTES);
  critic_kernel<<<kB, kThreads, SMEM_BYTES>>>(states, actions, b_embed,
                                              b_embed_q, outV, outW);
}